// round 3
// baseline (speedup 1.0000x reference)
#include <cuda_runtime.h>
#include <cuda_bf16.h>
#include <math.h>

// Problem constants
#define NN 8192      // nodes
#define TT 64        // timesteps
#define DIN 64       // input dim
#define RR 256       // reservoir dim
#define KTOT 320     // DIN + RR (fused GEMM K)
#define EE 131072    // edges
#define DOUT 64
#define HID 128      // 2*DOUT
#define CATD 1024    // (K+1)*R

// ---------------- device scratch (static allocations only) ----------------
__device__ float    d_H[2][NN * RR];              // 16 MB  double-buffered reservoir state
__device__ unsigned d_bitmap[NN * (NN / 32)];     // 8 MB   binary adjacency bitmap (256 words/row)
__device__ int      d_deg[NN];
__device__ int      d_rowptr[NN + 1];
__device__ int      d_col[2 * EE];                // CSR cols (ascending per row -> deterministic)
__device__ float    d_dinv[NN];
__device__ float    d_cat[NN * CATD];             // 32 MB  [h, Ah, A2h, A3h]
__device__ int      d_is64;

// ---------------- dtype detection for edge_index (int32 vs int64) ----------------
__global__ void detect_kernel(const unsigned* __restrict__ w) {
    if (threadIdx.x == 0) {
        int f = 1;
        for (int i = 0; i < 64; i++) {
            if (w[2 * i + 1] != 0u) { f = 0; break; }
        }
        d_is64 = f;  // values < 8192 => int64 high words all zero
    }
}

// ---------------- zero bitmap + H0 ----------------
__global__ void zero_kernel() {
    int i = blockIdx.x * blockDim.x + threadIdx.x;  // grid covers 2097152
    d_bitmap[i] = 0u;
    d_H[0][i] = 0.0f;
}

// ---------------- build binary adjacency bitmap ----------------
__global__ void pass1_kernel(const void* __restrict__ ei) {
    int i = blockIdx.x * blockDim.x + threadIdx.x;
    if (i >= 2 * EE) return;
    int u, v;
    if (d_is64) {
        const long long* p = (const long long*)ei;
        if (i < EE) { u = (int)p[i]; v = (int)p[EE + i]; }
        else        { u = (int)p[i]; v = (int)p[i - EE]; }   // p[i] == e1[i-EE]
    } else {
        const int* p = (const int*)ei;
        if (i < EE) { u = p[i]; v = p[EE + i]; }
        else        { u = p[i]; v = p[i - EE]; }
    }
    atomicOr(&d_bitmap[(u << 8) + (v >> 5)], 1u << (v & 31));
}

// ---------------- degree + dinv (warp per row, popcount) ----------------
__global__ void degdinv_kernel() {
    int gw = (blockIdx.x * blockDim.x + threadIdx.x) >> 5;
    int lane = threadIdx.x & 31;
    if (gw >= NN) return;
    const unsigned* row = d_bitmap + gw * 256;
    int c = 0;
#pragma unroll
    for (int j = 0; j < 8; j++) c += __popc(row[lane * 8 + j]);
#pragma unroll
    for (int o = 16; o; o >>= 1) c += __shfl_xor_sync(0xffffffffu, c, o);
    if (lane == 0) {
        d_deg[gw] = c;
        d_dinv[gw] = (c > 0) ? fminf(1e6f, 1.0f / sqrtf((float)c)) : 0.0f;
    }
}

// ---------------- exclusive scan of degrees -> rowptr (single block) ----------------
__global__ void scan_kernel() {
    __shared__ int s[1024];
    int tid = threadIdx.x;
    int loc[8]; int sum = 0;
#pragma unroll
    for (int j = 0; j < 8; j++) { loc[j] = d_deg[tid * 8 + j]; sum += loc[j]; }
    s[tid] = sum;
    __syncthreads();
    for (int off = 1; off < 1024; off <<= 1) {
        int t = 0;
        if (tid >= off) t = s[tid - off];
        __syncthreads();
        s[tid] += t;
        __syncthreads();
    }
    int run = (tid == 0) ? 0 : s[tid - 1];
    if (tid == 0) d_rowptr[0] = 0;
#pragma unroll
    for (int j = 0; j < 8; j++) { run += loc[j]; d_rowptr[tid * 8 + j + 1] = run; }
}

// ---------------- extract CSR cols from bitmap (warp per row, ascending order) ----------------
__global__ void extract_kernel() {
    int gw = (blockIdx.x * blockDim.x + threadIdx.x) >> 5;
    int lane = threadIdx.x & 31;
    if (gw >= NN) return;
    const unsigned* row = d_bitmap + gw * 256;
    unsigned w[8]; int cnt = 0;
#pragma unroll
    for (int j = 0; j < 8; j++) { w[j] = row[lane * 8 + j]; cnt += __popc(w[j]); }
    int off = cnt;
#pragma unroll
    for (int d = 1; d < 32; d <<= 1) {
        int t = __shfl_up_sync(0xffffffffu, off, d);
        if (lane >= d) off += t;
    }
    off -= cnt;  // exclusive prefix within warp; lanes cover ascending word chunks
    int pos = d_rowptr[gw] + off;
#pragma unroll
    for (int j = 0; j < 8; j++) {
        unsigned m = w[j];
        int base = (lane * 8 + j) << 5;
        while (m) {
            int b = __ffs(m) - 1;
            d_col[pos++] = base + b;
            m &= m - 1;
        }
    }
}

// ---------------- ESN step: Hout = 0.7*Hin + 0.3*tanh([X_t|Hin] @ [Win|Wres]^T) ----------------
// BM=128, BN=64, BK=16, 256 threads, 8x4 microtile per thread
__global__ __launch_bounds__(256) void step_kernel(
    const float* __restrict__ x, const float* __restrict__ Win,
    const float* __restrict__ Wres, int t)
{
    __shared__ float As[16][128 + 4];  // [k][m]
    __shared__ float Bs[16][64 + 4];   // [k][r]
    const float* Hin = d_H[t & 1];
    float* Hout = d_H[(t & 1) ^ 1];

    int tid = threadIdx.x;
    int m0 = blockIdx.x * 128;
    int n0 = blockIdx.y * 64;
    int tm = (tid >> 4) * 8;
    int tn = (tid & 15) * 4;

    float acc[8][4];
#pragma unroll
    for (int i = 0; i < 8; i++)
#pragma unroll
        for (int j = 0; j < 4; j++) acc[i][j] = 0.0f;

    int lm = tid >> 1;          // 0..127 (A loader row)
    int lka = (tid & 1) * 8;    // 0 or 8
    int ln = tid >> 2;          // 0..63  (B loader row = output col)
    int lkb = (tid & 3) * 4;    // 0,4,8,12

    const float* xrow = x + (size_t)(m0 + lm) * (TT * DIN) + t * DIN;
    const float* hrow = Hin + (m0 + lm) * RR;
    const float* wrow_in = Win + (n0 + ln) * DIN;
    const float* wrow_res = Wres + (n0 + ln) * RR;

#pragma unroll 1
    for (int kt = 0; kt < 20; kt++) {
        int k0 = kt * 16;
        // load A tile
        {
            int k = k0 + lka;
            float4 v0, v1;
            if (k < DIN) {
                v0 = *(const float4*)(xrow + k);
                v1 = *(const float4*)(xrow + k + 4);
            } else {
                v0 = *(const float4*)(hrow + (k - DIN));
                v1 = *(const float4*)(hrow + (k - DIN) + 4);
            }
            As[lka + 0][lm] = v0.x; As[lka + 1][lm] = v0.y;
            As[lka + 2][lm] = v0.z; As[lka + 3][lm] = v0.w;
            As[lka + 4][lm] = v1.x; As[lka + 5][lm] = v1.y;
            As[lka + 6][lm] = v1.z; As[lka + 7][lm] = v1.w;
        }
        // load B tile
        {
            int k = k0 + lkb;
            float4 v;
            if (k < DIN) v = *(const float4*)(wrow_in + k);
            else         v = *(const float4*)(wrow_res + (k - DIN));
            Bs[lkb + 0][ln] = v.x; Bs[lkb + 1][ln] = v.y;
            Bs[lkb + 2][ln] = v.z; Bs[lkb + 3][ln] = v.w;
        }
        __syncthreads();
#pragma unroll
        for (int kk = 0; kk < 16; kk++) {
            float4 a0 = *(const float4*)&As[kk][tm];
            float4 a1 = *(const float4*)&As[kk][tm + 4];
            float4 b4 = *(const float4*)&Bs[kk][tn];
            float av[8] = {a0.x, a0.y, a0.z, a0.w, a1.x, a1.y, a1.z, a1.w};
            float bv[4] = {b4.x, b4.y, b4.z, b4.w};
#pragma unroll
            for (int i = 0; i < 8; i++)
#pragma unroll
                for (int j = 0; j < 4; j++) acc[i][j] += av[i] * bv[j];
        }
        __syncthreads();
    }

    // epilogue: leaky tanh update
#pragma unroll
    for (int i = 0; i < 8; i++) {
        int row = m0 + tm + i;
        const float4 h4 = *(const float4*)(Hin + row * RR + n0 + tn);
        float4 o;
        o.x = 0.7f * h4.x + 0.3f * tanhf(acc[i][0]);
        o.y = 0.7f * h4.y + 0.3f * tanhf(acc[i][1]);
        o.z = 0.7f * h4.z + 0.3f * tanhf(acc[i][2]);
        o.w = 0.7f * h4.w + 0.3f * tanhf(acc[i][3]);
        *(float4*)(Hout + row * RR + n0 + tn) = o;
    }
}

// ---------------- copy final H into cat[:, 0:256] ----------------
__global__ void copy_kernel() {
    int i = blockIdx.x * blockDim.x + threadIdx.x;  // covers NN*RR = 2097152
    int n = i >> 8, r = i & 255;
    d_cat[n * CATD + r] = d_H[0][i];
}

// ---------------- SpMM hop: cat[:, hop] = dinv .* (A_bin @ (dinv .* cat[:, hop-1])) ----------------
__global__ __launch_bounds__(256) void spmm_kernel(int hop) {
    int u = blockIdx.x;
    int r = threadIdx.x;
    int s = d_rowptr[u], e = d_rowptr[u + 1];
    const float* src = d_cat + (hop - 1) * RR + r;
    float acc = 0.0f;
    int i = s;
    for (; i + 4 <= e; i += 4) {
        int v0 = d_col[i], v1 = d_col[i + 1], v2 = d_col[i + 2], v3 = d_col[i + 3];
        float x0 = src[(size_t)v0 * CATD];
        float x1 = src[(size_t)v1 * CATD];
        float x2 = src[(size_t)v2 * CATD];
        float x3 = src[(size_t)v3 * CATD];
        acc += d_dinv[v0] * x0 + d_dinv[v1] * x1 + d_dinv[v2] * x2 + d_dinv[v3] * x3;
    }
    for (; i < e; i++) {
        int v = d_col[i];
        acc += d_dinv[v] * src[(size_t)v * CATD];
    }
    d_cat[u * CATD + hop * RR + r] = d_dinv[u] * acc;
}

// ---------------- readout: GELU(cat@W1^T+b1)@W2^T+b2 -> LayerNorm -> out ----------------
// 64 nodes per block, 256 threads
__global__ __launch_bounds__(256) void readout_kernel(
    const float* __restrict__ W1, const float* __restrict__ b1,
    const float* __restrict__ W2, const float* __restrict__ b2,
    const float* __restrict__ gamma, const float* __restrict__ beta,
    float* __restrict__ out)
{
    __shared__ float As1[16][64 + 4];    // [k][m]
    __shared__ float Bs1[16][128 + 4];   // [k][j]
    __shared__ float z1t[128][64 + 4];   // [col][row] transposed hidden

    int tid = threadIdx.x;
    int n0 = blockIdx.x * 64;

    // ---- GEMM1: [64,1024] @ [1024,128] ----
    int rg = tid >> 5;   // 0..7  (8 rows each)
    int cg = tid & 31;   // 0..31 (4 cols each)
    float acc[8][4];
#pragma unroll
    for (int i = 0; i < 8; i++)
#pragma unroll
        for (int j = 0; j < 4; j++) acc[i][j] = 0.0f;

    int lm = tid >> 2;        // 0..63, A loader row
    int lka = (tid & 3) * 4;  // 0,4,8,12
    int lj = tid >> 1;        // 0..127, B loader row
    int lkb = (tid & 1) * 8;  // 0 or 8
    const float* arow = d_cat + (n0 + lm) * CATD;
    const float* brow = W1 + lj * CATD;

#pragma unroll 1
    for (int kt = 0; kt < 64; kt++) {
        int k0 = kt * 16;
        float4 va = *(const float4*)(arow + k0 + lka);
        As1[lka + 0][lm] = va.x; As1[lka + 1][lm] = va.y;
        As1[lka + 2][lm] = va.z; As1[lka + 3][lm] = va.w;
        float4 vb0 = *(const float4*)(brow + k0 + lkb);
        float4 vb1 = *(const float4*)(brow + k0 + lkb + 4);
        Bs1[lkb + 0][lj] = vb0.x; Bs1[lkb + 1][lj] = vb0.y;
        Bs1[lkb + 2][lj] = vb0.z; Bs1[lkb + 3][lj] = vb0.w;
        Bs1[lkb + 4][lj] = vb1.x; Bs1[lkb + 5][lj] = vb1.y;
        Bs1[lkb + 6][lj] = vb1.z; Bs1[lkb + 7][lj] = vb1.w;
        __syncthreads();
#pragma unroll
        for (int kk = 0; kk < 16; kk++) {
            float4 a0 = *(const float4*)&As1[kk][rg * 8];
            float4 a1 = *(const float4*)&As1[kk][rg * 8 + 4];
            float4 b4 = *(const float4*)&Bs1[kk][cg * 4];
            float av[8] = {a0.x, a0.y, a0.z, a0.w, a1.x, a1.y, a1.z, a1.w};
            float bv[4] = {b4.x, b4.y, b4.z, b4.w};
#pragma unroll
            for (int i = 0; i < 8; i++)
#pragma unroll
                for (int j = 0; j < 4; j++) acc[i][j] += av[i] * bv[j];
        }
        __syncthreads();
    }

    // bias + exact GELU, store transposed
#pragma unroll
    for (int i = 0; i < 8; i++) {
#pragma unroll
        for (int j = 0; j < 4; j++) {
            int col = cg * 4 + j;
            int row = rg * 8 + i;
            float v = acc[i][j] + b1[col];
            float g = 0.5f * v * (1.0f + erff(v * 0.70710678118654752f));
            z1t[col][row] = g;
        }
    }
    __syncthreads();

    // ---- GEMM2: [64,128] @ [128,64] ----
    int rg2 = tid >> 4;  // 0..15 (4 rows each)
    int cg2 = tid & 15;  // 0..15 (4 cols each)
    float acc2[4][4];
#pragma unroll
    for (int i = 0; i < 4; i++)
#pragma unroll
        for (int j = 0; j < 4; j++) acc2[i][j] = 0.0f;

#pragma unroll 4
    for (int k = 0; k < 128; k++) {
        float4 a = *(const float4*)&z1t[k][rg2 * 4];
        float av[4] = {a.x, a.y, a.z, a.w};
#pragma unroll
        for (int j = 0; j < 4; j++) {
            float b = __ldg(&W2[(cg2 * 4 + j) * 128 + k]);
#pragma unroll
            for (int i = 0; i < 4; i++) acc2[i][j] += av[i] * b;
        }
    }

    // bias
    float vals[4][4];
#pragma unroll
    for (int i = 0; i < 4; i++)
#pragma unroll
        for (int j = 0; j < 4; j++) vals[i][j] = acc2[i][j] + b2[cg2 * 4 + j];

    // ---- LayerNorm over 64 cols: reduce across the 16 cg2 thread-groups via shfl ----
    float mean[4], var[4];
#pragma unroll
    for (int i = 0; i < 4; i++) {
        float s = vals[i][0] + vals[i][1] + vals[i][2] + vals[i][3];
#pragma unroll
        for (int o = 8; o; o >>= 1) s += __shfl_xor_sync(0xffffffffu, s, o);
        mean[i] = s * (1.0f / 64.0f);
    }
#pragma unroll
    for (int i = 0; i < 4; i++) {
        float s = 0.0f;
#pragma unroll
        for (int j = 0; j < 4; j++) {
            float d = vals[i][j] - mean[i];
            s += d * d;
        }
#pragma unroll
        for (int o = 8; o; o >>= 1) s += __shfl_xor_sync(0xffffffffu, s, o);
        var[i] = s * (1.0f / 64.0f);
    }

#pragma unroll
    for (int i = 0; i < 4; i++) {
        int node = n0 + rg2 * 4 + i;
        float inv = 1.0f / sqrtf(var[i] + 1e-5f);
        float4 o;
        float g0 = gamma[cg2 * 4 + 0], g1 = gamma[cg2 * 4 + 1];
        float g2 = gamma[cg2 * 4 + 2], g3 = gamma[cg2 * 4 + 3];
        float be0 = beta[cg2 * 4 + 0], be1 = beta[cg2 * 4 + 1];
        float be2 = beta[cg2 * 4 + 2], be3 = beta[cg2 * 4 + 3];
        o.x = (vals[i][0] - mean[i]) * inv * g0 + be0;
        o.y = (vals[i][1] - mean[i]) * inv * g1 + be1;
        o.z = (vals[i][2] - mean[i]) * inv * g2 + be2;
        o.w = (vals[i][3] - mean[i]) * inv * g3 + be3;
        *(float4*)&out[node * DOUT + cg2 * 4] = o;
    }
}

// ---------------- launch ----------------
extern "C" void kernel_launch(void* const* d_in, const int* in_sizes, int n_in,
                              void* d_out, int out_size) {
    const float* x     = (const float*)d_in[0];
    const void*  ei    = d_in[1];
    const float* Win   = (const float*)d_in[2];
    const float* Wres  = (const float*)d_in[3];
    const float* W1    = (const float*)d_in[4];
    const float* b1    = (const float*)d_in[5];
    const float* W2    = (const float*)d_in[6];
    const float* b2    = (const float*)d_in[7];
    const float* gamma = (const float*)d_in[8];
    const float* beta  = (const float*)d_in[9];
    float* out = (float*)d_out;

    detect_kernel<<<1, 32>>>((const unsigned*)ei);
    zero_kernel<<<4096, 512>>>();                 // 2097152 threads: bitmap + H0
    pass1_kernel<<<1024, 256>>>(ei);              // 2E = 262144 edge directions
    degdinv_kernel<<<1024, 256>>>();              // 8192 warps (1 per row)
    scan_kernel<<<1, 1024>>>();
    extract_kernel<<<1024, 256>>>();              // 8192 warps (1 per row)

    for (int t = 0; t < TT; t++)
        step_kernel<<<dim3(64, 4), 256>>>(x, Win, Wres, t);

    copy_kernel<<<4096, 512>>>();

    for (int hop = 1; hop <= 3; hop++)
        spmm_kernel<<<NN, 256>>>(hop);

    readout_kernel<<<128, 256>>>(W1, b1, W2, b2, gamma, beta, out);
}

// round 7
// speedup vs baseline: 1.6653x; 1.6653x over previous
#include <cuda_runtime.h>
#include <cuda_bf16.h>
#include <stdint.h>
#include <math.h>

// Problem constants
#define NN 8192      // nodes
#define TT 64        // timesteps
#define DIN 64       // input dim
#define RR 256       // reservoir dim
#define EE 131072    // edges
#define DOUT 64
#define CATD 1024    // (K+1)*R

// step-kernel tiling
#define AROWB 80                 // smem bytes per 32-bf16 row (64B data + 16B pad)
#define ATILE (128 * AROWB)      // 10240 B per operand tile
#define BUFSZ (4 * ATILE)        // A_hi | A_lo | B_hi | B_lo
#define STEP_SMEM (2 * BUFSZ)    // double buffered: 81920 B

// ---------------- device scratch (static allocations only) ----------------
__device__ float           d_H[2][NN * RR];      // fp32 reservoir state (ping/pong)
__device__ __nv_bfloat16   d_Hhi[2][NN * RR];    // bf16 hi of H
__device__ __nv_bfloat16   d_Hlo[2][NN * RR];    // bf16 lo of H
__device__ __nv_bfloat16   d_Bhi[RR * 320];      // [Win|Wres] bf16 hi, [256][320]
__device__ __nv_bfloat16   d_Blo[RR * 320];
__device__ unsigned d_bitmap[NN * (NN / 32)];
__device__ int      d_deg[NN];
__device__ int      d_rowptr[NN + 1];
__device__ int      d_col[2 * EE];
__device__ float    d_dinv[NN];
__device__ float    d_cat[NN * CATD];
__device__ int      d_is64;

// ================= PTX helpers (sm_80-compatible only) =================
__device__ __forceinline__ uint32_t s2u(const void* p) {
    uint32_t a;
    asm("{ .reg .u64 t; cvta.to.shared.u64 t, %1; cvt.u32.u64 %0, t; }" : "=r"(a) : "l"(p));
    return a;
}
#define LDSM4(r, addr) \
    asm volatile("ldmatrix.sync.aligned.m8n8.x4.shared.b16 {%0,%1,%2,%3}, [%4];" \
        : "=r"((r)[0]), "=r"((r)[1]), "=r"((r)[2]), "=r"((r)[3]) : "r"(addr))

#define MMA16816(d, a, b0, b1) \
    asm volatile("mma.sync.aligned.m16n8k16.row.col.f32.bf16.bf16.f32 " \
        "{%0,%1,%2,%3}, {%4,%5,%6,%7}, {%8,%9}, {%0,%1,%2,%3};" \
        : "+f"((d)[0]), "+f"((d)[1]), "+f"((d)[2]), "+f"((d)[3]) \
        : "r"((a)[0]), "r"((a)[1]), "r"((a)[2]), "r"((a)[3]), "r"(b0), "r"(b1))

__device__ __forceinline__ float ftanh(float v) {
    // tanh(v) = sign(v) * (1 - e) / (1 + e),  e = exp(-2|v|) <= 1 (no overflow)
    float a = fabsf(v);
    float e = __expf(-2.0f * a);
    float r = __fdividef(1.0f - e, 1.0f + e);
    return copysignf(r, v);
}

// ---------------- dtype detection for edge_index (int32 vs int64) ----------------
__global__ void detect_kernel(const unsigned* __restrict__ w) {
    if (threadIdx.x == 0) {
        int f = 1;
        for (int i = 0; i < 64; i++) {
            if (w[2 * i + 1] != 0u) { f = 0; break; }
        }
        d_is64 = f;  // values < 8192 => int64 high words all zero
    }
}

// ---------------- zero bitmap + H0 (fp32 and bf16 hi/lo) ----------------
__global__ void zero_kernel() {
    int i = blockIdx.x * blockDim.x + threadIdx.x;  // 2097152 threads
    d_bitmap[i] = 0u;
    d_H[0][i] = 0.0f;
    d_Hhi[0][i] = __nv_bfloat16(0.0f);
    d_Hlo[0][i] = __nv_bfloat16(0.0f);
}

// ---------------- weight conversion to bf16 hi/lo ----------------
__global__ void wconv_kernel(const float* __restrict__ Win, const float* __restrict__ Wres) {
    int i = blockIdx.x * blockDim.x + threadIdx.x;
    if (i >= 256 * 320) return;
    int r = i / 320, k = i % 320;
    float v = (k < DIN) ? Win[r * DIN + k] : Wres[r * RR + (k - DIN)];
    __nv_bfloat16 h = __float2bfloat16(v);
    d_Bhi[i] = h;
    d_Blo[i] = __float2bfloat16(v - __bfloat162float(h));
}

// ---------------- build binary adjacency bitmap ----------------
__global__ void pass1_kernel(const void* __restrict__ ei) {
    int i = blockIdx.x * blockDim.x + threadIdx.x;
    if (i >= 2 * EE) return;
    int u, v;
    if (d_is64) {
        const long long* p = (const long long*)ei;
        if (i < EE) { u = (int)p[i]; v = (int)p[EE + i]; }
        else        { u = (int)p[i]; v = (int)p[i - EE]; }
    } else {
        const int* p = (const int*)ei;
        if (i < EE) { u = p[i]; v = p[EE + i]; }
        else        { u = p[i]; v = p[i - EE]; }
    }
    atomicOr(&d_bitmap[(u << 8) + (v >> 5)], 1u << (v & 31));
}

// ---------------- degree + dinv ----------------
__global__ void degdinv_kernel() {
    int gw = (blockIdx.x * blockDim.x + threadIdx.x) >> 5;
    int lane = threadIdx.x & 31;
    if (gw >= NN) return;
    const unsigned* row = d_bitmap + gw * 256;
    int c = 0;
#pragma unroll
    for (int j = 0; j < 8; j++) c += __popc(row[lane * 8 + j]);
#pragma unroll
    for (int o = 16; o; o >>= 1) c += __shfl_xor_sync(0xffffffffu, c, o);
    if (lane == 0) {
        d_deg[gw] = c;
        d_dinv[gw] = (c > 0) ? fminf(1e6f, 1.0f / sqrtf((float)c)) : 0.0f;
    }
}

// ---------------- exclusive scan -> rowptr ----------------
__global__ void scan_kernel() {
    __shared__ int s[1024];
    int tid = threadIdx.x;
    int loc[8]; int sum = 0;
#pragma unroll
    for (int j = 0; j < 8; j++) { loc[j] = d_deg[tid * 8 + j]; sum += loc[j]; }
    s[tid] = sum;
    __syncthreads();
    for (int off = 1; off < 1024; off <<= 1) {
        int t = 0;
        if (tid >= off) t = s[tid - off];
        __syncthreads();
        s[tid] += t;
        __syncthreads();
    }
    int run = (tid == 0) ? 0 : s[tid - 1];
    if (tid == 0) d_rowptr[0] = 0;
#pragma unroll
    for (int j = 0; j < 8; j++) { run += loc[j]; d_rowptr[tid * 8 + j + 1] = run; }
}

// ---------------- extract CSR cols ----------------
__global__ void extract_kernel() {
    int gw = (blockIdx.x * blockDim.x + threadIdx.x) >> 5;
    int lane = threadIdx.x & 31;
    if (gw >= NN) return;
    const unsigned* row = d_bitmap + gw * 256;
    unsigned w[8]; int cnt = 0;
#pragma unroll
    for (int j = 0; j < 8; j++) { w[j] = row[lane * 8 + j]; cnt += __popc(w[j]); }
    int off = cnt;
#pragma unroll
    for (int d = 1; d < 32; d <<= 1) {
        int t = __shfl_up_sync(0xffffffffu, off, d);
        if (lane >= d) off += t;
    }
    off -= cnt;
    int pos = d_rowptr[gw] + off;
#pragma unroll
    for (int j = 0; j < 8; j++) {
        unsigned m = w[j];
        int base = (lane * 8 + j) << 5;
        while (m) {
            int b = __ffs(m) - 1;
            d_col[pos++] = base + b;
            m &= m - 1;
        }
    }
}

// ================= ESN step via mma.sync (bf16 hi/lo split) =================
// CTA tile M=128, N=128; 8 warps as 4(m) x 2(n), each warp 32x64.
// K=320 in 10 chunks of 32 (chunks 0,1 from x fp32->bf16; 2..9 from Hhi/Hlo).
// Double-buffered smem with register prefetch of next chunk during MMA.

// ---- chunk load/store helpers ----
__device__ __forceinline__ void issueA_H(int c, int m0, int tid,
                                         const __nv_bfloat16* Hhi, const __nv_bfloat16* Hlo,
                                         uint4* p) {
#pragma unroll
    for (int i = 0; i < 2; i++) {
        int g = tid * 2 + i, row = g >> 2, q = g & 3;
        size_t e = (size_t)(m0 + row) * RR + (c - 2) * 32 + q * 8;
        p[i]     = *(const uint4*)((const char*)Hhi + e * 2);
        p[2 + i] = *(const uint4*)((const char*)Hlo + e * 2);
    }
}
__device__ __forceinline__ void issueA_X(const float* x, int t, int c, int m0, int tid, float4* p) {
#pragma unroll
    for (int i = 0; i < 4; i++) {
        int g = tid * 4 + i, row = g >> 3, q = g & 7;
        p[i] = *(const float4*)(x + (size_t)(m0 + row) * (TT * DIN) + t * DIN + c * 32 + q * 4);
    }
}
__device__ __forceinline__ void issueB(int c, int n0, int tid, uint4* p) {
#pragma unroll
    for (int i = 0; i < 2; i++) {
        int g = tid * 2 + i, row = g >> 2, q = g & 3;
        size_t e = (size_t)(n0 + row) * 320 + c * 32 + q * 8;
        p[i]     = *(const uint4*)((const char*)d_Bhi + e * 2);
        p[2 + i] = *(const uint4*)((const char*)d_Blo + e * 2);
    }
}
__device__ __forceinline__ void storeA_H(char* buf, int tid, const uint4* p) {
#pragma unroll
    for (int i = 0; i < 2; i++) {
        int g = tid * 2 + i, row = g >> 2, q = g & 3;
        *(uint4*)(buf + row * AROWB + q * 16) = p[i];
        *(uint4*)(buf + ATILE + row * AROWB + q * 16) = p[2 + i];
    }
}
__device__ __forceinline__ void storeA_X(char* buf, int tid, const float4* p) {
#pragma unroll
    for (int i = 0; i < 4; i++) {
        int g = tid * 4 + i, row = g >> 3, q = g & 7;
        float4 v = p[i];
        union { __nv_bfloat16 bb[4]; uint2 u; } uh, ul;
        uh.bb[0] = __float2bfloat16(v.x); uh.bb[1] = __float2bfloat16(v.y);
        uh.bb[2] = __float2bfloat16(v.z); uh.bb[3] = __float2bfloat16(v.w);
        ul.bb[0] = __float2bfloat16(v.x - __bfloat162float(uh.bb[0]));
        ul.bb[1] = __float2bfloat16(v.y - __bfloat162float(uh.bb[1]));
        ul.bb[2] = __float2bfloat16(v.z - __bfloat162float(uh.bb[2]));
        ul.bb[3] = __float2bfloat16(v.w - __bfloat162float(uh.bb[3]));
        *(uint2*)(buf + row * AROWB + q * 8) = uh.u;
        *(uint2*)(buf + ATILE + row * AROWB + q * 8) = ul.u;
    }
}
__device__ __forceinline__ void storeB(char* buf, int tid, const uint4* p) {
#pragma unroll
    for (int i = 0; i < 2; i++) {
        int g = tid * 2 + i, row = g >> 2, q = g & 3;
        *(uint4*)(buf + 2 * ATILE + row * AROWB + q * 16) = p[i];
        *(uint4*)(buf + 3 * ATILE + row * AROWB + q * 16) = p[2 + i];
    }
}

__global__ void __launch_bounds__(256)
step_tc(const float* __restrict__ x, int t)
{
    extern __shared__ __align__(128) char smem[];
    const int tid = threadIdx.x, wid = tid >> 5, lane = tid & 31;
    const int m0 = blockIdx.x * 128, n0 = blockIdx.y * 128;
    const int warpM = (wid & 3) * 32, warpN = (wid >> 2) * 64;

    const float* __restrict__ Hin = d_H[t & 1];
    float* __restrict__ Hout = d_H[(t & 1) ^ 1];
    const __nv_bfloat16* __restrict__ Hhi = d_Hhi[t & 1];
    const __nv_bfloat16* __restrict__ Hlo = d_Hlo[t & 1];
    __nv_bfloat16* __restrict__ HhiO = d_Hhi[(t & 1) ^ 1];
    __nv_bfloat16* __restrict__ HloO = d_Hlo[(t & 1) ^ 1];

    char* buf0 = smem;
    char* buf1 = smem + BUFSZ;

    // preload chunk 0 (x-sourced)
    {
        float4 px[4]; uint4 pb[4];
        issueA_X(x, t, 0, m0, tid, px);
        issueB(0, n0, tid, pb);
        storeA_X(buf0, tid, px);
        storeB(buf0, tid, pb);
    }
    __syncthreads();

    float acc[2][8][4];
#pragma unroll
    for (int mi = 0; mi < 2; mi++)
#pragma unroll
        for (int ni = 0; ni < 8; ni++)
#pragma unroll
            for (int q = 0; q < 4; q++) acc[mi][ni][q] = 0.0f;

#pragma unroll 1
    for (int c = 0; c < 10; c++) {
        char* cur = (c & 1) ? buf1 : buf0;
        char* nxt = (c & 1) ? buf0 : buf1;
        const bool hasNext = (c < 9);

        float4 px[4]; uint4 pa[4]; uint4 pb[4];
        if (hasNext) {
            if (c + 1 == 1) issueA_X(x, t, 1, m0, tid, px);
            else            issueA_H(c + 1, m0, tid, Hhi, Hlo, pa);
            issueB(c + 1, n0, tid, pb);
        }

        const uint32_t sbuf = s2u(cur);
#pragma unroll
        for (int ks = 0; ks < 2; ks++) {
            const int k = ks * 16;
            // A fragments (hi & lo), 2 m16 tiles
            uint32_t ah[2][4], al[2][4];
#pragma unroll
            for (int mi = 0; mi < 2; mi++) {
                int row = warpM + mi * 16 + (lane & 15);
                int col = k + (lane >> 4) * 8;
                uint32_t ad = sbuf + row * AROWB + col * 2;
                LDSM4(ah[mi], ad);
                LDSM4(al[mi], ad + ATILE);
            }
            // B fragments in pairs of n8 tiles + MMA
#pragma unroll
            for (int nb = 0; nb < 4; nb++) {
                int row = warpN + nb * 16 + ((lane >> 4) << 3) + (lane & 7);
                int col = k + ((lane >> 3) & 1) * 8;
                uint32_t bd = sbuf + 2 * ATILE + row * AROWB + col * 2;
                uint32_t bh[4], bl[4];
                LDSM4(bh, bd);
                LDSM4(bl, bd + ATILE);
#pragma unroll
                for (int mi = 0; mi < 2; mi++) {
                    MMA16816(acc[mi][nb * 2], ah[mi], bh[0], bh[1]);
                    MMA16816(acc[mi][nb * 2], ah[mi], bl[0], bl[1]);
                    MMA16816(acc[mi][nb * 2], al[mi], bh[0], bh[1]);
                    MMA16816(acc[mi][nb * 2 + 1], ah[mi], bh[2], bh[3]);
                    MMA16816(acc[mi][nb * 2 + 1], ah[mi], bl[2], bl[3]);
                    MMA16816(acc[mi][nb * 2 + 1], al[mi], bh[2], bh[3]);
                }
            }
        }

        if (hasNext) {
            if (c + 1 == 1) storeA_X(nxt, tid, px);
            else            storeA_H(nxt, tid, pa);
            storeB(nxt, tid, pb);
        }
        __syncthreads();
    }

    // ---- epilogue: leaky tanh update ----
#pragma unroll
    for (int mi = 0; mi < 2; mi++) {
#pragma unroll
        for (int ni = 0; ni < 8; ni++) {
            int r = m0 + warpM + mi * 16 + (lane >> 2);
            int col = n0 + warpN + ni * 8 + (lane & 3) * 2;
#pragma unroll
            for (int rr = 0; rr < 2; rr++) {
                int row = r + rr * 8;
                float v0 = acc[mi][ni][rr * 2 + 0];
                float v1 = acc[mi][ni][rr * 2 + 1];
                size_t base = (size_t)row * RR + col;
                float2 h2 = *(const float2*)(Hin + base);
                float o0 = 0.7f * h2.x + 0.3f * ftanh(v0);
                float o1 = 0.7f * h2.y + 0.3f * ftanh(v1);
                if (t == TT - 1) {
                    *(float2*)&d_cat[(size_t)row * CATD + col] = make_float2(o0, o1);
                } else {
                    *(float2*)(Hout + base) = make_float2(o0, o1);
                    union { __nv_bfloat16 bb[2]; uint32_t u; } uh, ul;
                    uh.bb[0] = __float2bfloat16(o0);
                    uh.bb[1] = __float2bfloat16(o1);
                    ul.bb[0] = __float2bfloat16(o0 - __bfloat162float(uh.bb[0]));
                    ul.bb[1] = __float2bfloat16(o1 - __bfloat162float(uh.bb[1]));
                    *(uint32_t*)((char*)HhiO + base * 2) = uh.u;
                    *(uint32_t*)((char*)HloO + base * 2) = ul.u;
                }
            }
        }
    }
}

// ---------------- SpMM hop ----------------
__global__ __launch_bounds__(256) void spmm_kernel(int hop) {
    int u = blockIdx.x;
    int r = threadIdx.x;
    int s = d_rowptr[u], e = d_rowptr[u + 1];
    const float* src = d_cat + (hop - 1) * RR + r;
    float acc = 0.0f;
    int i = s;
    for (; i + 4 <= e; i += 4) {
        int v0 = d_col[i], v1 = d_col[i + 1], v2 = d_col[i + 2], v3 = d_col[i + 3];
        float x0 = src[(size_t)v0 * CATD];
        float x1 = src[(size_t)v1 * CATD];
        float x2 = src[(size_t)v2 * CATD];
        float x3 = src[(size_t)v3 * CATD];
        acc += d_dinv[v0] * x0 + d_dinv[v1] * x1 + d_dinv[v2] * x2 + d_dinv[v3] * x3;
    }
    for (; i < e; i++) {
        int v = d_col[i];
        acc += d_dinv[v] * src[(size_t)v * CATD];
    }
    d_cat[u * CATD + hop * RR + r] = d_dinv[u] * acc;
}

// ---------------- readout (fp32 SIMT) ----------------
__global__ __launch_bounds__(256) void readout_kernel(
    const float* __restrict__ W1, const float* __restrict__ b1,
    const float* __restrict__ W2, const float* __restrict__ b2,
    const float* __restrict__ gamma, const float* __restrict__ beta,
    float* __restrict__ out)
{
    __shared__ float As1[16][64 + 4];
    __shared__ float Bs1[16][128 + 4];
    __shared__ float z1t[128][64 + 4];

    int tid = threadIdx.x;
    int n0 = blockIdx.x * 64;

    int rg = tid >> 5;
    int cg = tid & 31;
    float acc[8][4];
#pragma unroll
    for (int i = 0; i < 8; i++)
#pragma unroll
        for (int j = 0; j < 4; j++) acc[i][j] = 0.0f;

    int lm = tid >> 2;
    int lka = (tid & 3) * 4;
    int lj = tid >> 1;
    int lkb = (tid & 1) * 8;
    const float* arow = d_cat + (n0 + lm) * CATD;
    const float* brow = W1 + lj * CATD;

#pragma unroll 1
    for (int kt = 0; kt < 64; kt++) {
        int k0 = kt * 16;
        float4 va = *(const float4*)(arow + k0 + lka);
        As1[lka + 0][lm] = va.x; As1[lka + 1][lm] = va.y;
        As1[lka + 2][lm] = va.z; As1[lka + 3][lm] = va.w;
        float4 vb0 = *(const float4*)(brow + k0 + lkb);
        float4 vb1 = *(const float4*)(brow + k0 + lkb + 4);
        Bs1[lkb + 0][lj] = vb0.x; Bs1[lkb + 1][lj] = vb0.y;
        Bs1[lkb + 2][lj] = vb0.z; Bs1[lkb + 3][lj] = vb0.w;
        Bs1[lkb + 4][lj] = vb1.x; Bs1[lkb + 5][lj] = vb1.y;
        Bs1[lkb + 6][lj] = vb1.z; Bs1[lkb + 7][lj] = vb1.w;
        __syncthreads();
#pragma unroll
        for (int kk = 0; kk < 16; kk++) {
            float4 a0 = *(const float4*)&As1[kk][rg * 8];
            float4 a1 = *(const float4*)&As1[kk][rg * 8 + 4];
            float4 b4 = *(const float4*)&Bs1[kk][cg * 4];
            float av[8] = {a0.x, a0.y, a0.z, a0.w, a1.x, a1.y, a1.z, a1.w};
            float bv[4] = {b4.x, b4.y, b4.z, b4.w};
#pragma unroll
            for (int i = 0; i < 8; i++)
#pragma unroll
                for (int j = 0; j < 4; j++) acc[i][j] += av[i] * bv[j];
        }
        __syncthreads();
    }

#pragma unroll
    for (int i = 0; i < 8; i++) {
#pragma unroll
        for (int j = 0; j < 4; j++) {
            int col = cg * 4 + j;
            int row = rg * 8 + i;
            float v = acc[i][j] + b1[col];
            float g = 0.5f * v * (1.0f + erff(v * 0.70710678118654752f));
            z1t[col][row] = g;
        }
    }
    __syncthreads();

    int rg2 = tid >> 4;
    int cg2 = tid & 15;
    float acc2[4][4];
#pragma unroll
    for (int i = 0; i < 4; i++)
#pragma unroll
        for (int j = 0; j < 4; j++) acc2[i][j] = 0.0f;

#pragma unroll 4
    for (int k = 0; k < 128; k++) {
        float4 a = *(const float4*)&z1t[k][rg2 * 4];
        float av[4] = {a.x, a.y, a.z, a.w};
#pragma unroll
        for (int j = 0; j < 4; j++) {
            float b = __ldg(&W2[(cg2 * 4 + j) * 128 + k]);
#pragma unroll
            for (int i = 0; i < 4; i++) acc2[i][j] += av[i] * b;
        }
    }

    float vals[4][4];
#pragma unroll
    for (int i = 0; i < 4; i++)
#pragma unroll
        for (int j = 0; j < 4; j++) vals[i][j] = acc2[i][j] + b2[cg2 * 4 + j];

    float mean[4], var[4];
#pragma unroll
    for (int i = 0; i < 4; i++) {
        float s = vals[i][0] + vals[i][1] + vals[i][2] + vals[i][3];
#pragma unroll
        for (int o = 8; o; o >>= 1) s += __shfl_xor_sync(0xffffffffu, s, o);
        mean[i] = s * (1.0f / 64.0f);
    }
#pragma unroll
    for (int i = 0; i < 4; i++) {
        float s = 0.0f;
#pragma unroll
        for (int j = 0; j < 4; j++) {
            float d = vals[i][j] - mean[i];
            s += d * d;
        }
#pragma unroll
        for (int o = 8; o; o >>= 1) s += __shfl_xor_sync(0xffffffffu, s, o);
        var[i] = s * (1.0f / 64.0f);
    }

#pragma unroll
    for (int i = 0; i < 4; i++) {
        int node = n0 + rg2 * 4 + i;
        float inv = 1.0f / sqrtf(var[i] + 1e-5f);
        float4 o;
        float g0 = gamma[cg2 * 4 + 0], g1 = gamma[cg2 * 4 + 1];
        float g2 = gamma[cg2 * 4 + 2], g3 = gamma[cg2 * 4 + 3];
        float be0 = beta[cg2 * 4 + 0], be1 = beta[cg2 * 4 + 1];
        float be2 = beta[cg2 * 4 + 2], be3 = beta[cg2 * 4 + 3];
        o.x = (vals[i][0] - mean[i]) * inv * g0 + be0;
        o.y = (vals[i][1] - mean[i]) * inv * g1 + be1;
        o.z = (vals[i][2] - mean[i]) * inv * g2 + be2;
        o.w = (vals[i][3] - mean[i]) * inv * g3 + be3;
        *(float4*)&out[node * DOUT + cg2 * 4] = o;
    }
}

// ---------------- launch ----------------
extern "C" void kernel_launch(void* const* d_in, const int* in_sizes, int n_in,
                              void* d_out, int out_size) {
    const float* x     = (const float*)d_in[0];
    const void*  ei    = d_in[1];
    const float* Win   = (const float*)d_in[2];
    const float* Wres  = (const float*)d_in[3];
    const float* W1    = (const float*)d_in[4];
    const float* b1    = (const float*)d_in[5];
    const float* W2    = (const float*)d_in[6];
    const float* b2    = (const float*)d_in[7];
    const float* gamma = (const float*)d_in[8];
    const float* beta  = (const float*)d_in[9];
    float* out = (float*)d_out;

    (void)cudaFuncSetAttribute(step_tc, cudaFuncAttributeMaxDynamicSharedMemorySize, STEP_SMEM);

    detect_kernel<<<1, 32>>>((const unsigned*)ei);
    zero_kernel<<<4096, 512>>>();
    wconv_kernel<<<320, 256>>>(Win, Wres);
    pass1_kernel<<<1024, 256>>>(ei);
    degdinv_kernel<<<1024, 256>>>();
    scan_kernel<<<1, 1024>>>();
    extract_kernel<<<1024, 256>>>();

    for (int t = 0; t < TT; t++)
        step_tc<<<dim3(64, 2), 256, STEP_SMEM>>>(x, t);

    for (int hop = 1; hop <= 3; hop++)
        spmm_kernel<<<NN, 256>>>(hop);

    readout_kernel<<<128, 256>>>(W1, b1, W2, b2, gamma, beta, out);
}

// round 9
// speedup vs baseline: 1.8396x; 1.1047x over previous
#include <cuda_runtime.h>
#include <cuda_bf16.h>
#include <stdint.h>
#include <math.h>

// Problem constants
#define NN 8192      // nodes
#define TT 64        // timesteps
#define DIN 64       // input dim
#define RR 256       // reservoir dim
#define EE 131072    // edges
#define DOUT 64
#define CATD 1024    // (K+1)*R

// persistent step kernel tiling: CTA = 64 rows x 256 cols, K=320 in 10 chunks of 32
#define MTILE 64
#define AROW 80                      // smem bytes per 32-bf16 row (64B data + 16B pad)
#define ACH  (MTILE * AROW)          // 5120 B  (one chunk, one type)
#define ACH2 (2 * ACH)               // 10240 B (hi+lo per chunk)
#define AREG (10 * ACH2)             // 102400 B resident A region
#define BTYPE (256 * AROW)           // 20480 B (one chunk, one type)
#define BBUF (2 * BTYPE)             // 40960 B per buffer (hi+lo)
#define STEP_SMEM (AREG + 2 * BBUF)  // 184320 B

// ---------------- device scratch (static allocations only) ----------------
__device__ __align__(16) __nv_bfloat16 d_Bhi[RR * 320];   // [Win|Wres] bf16 hi, [256][320]
__device__ __align__(16) __nv_bfloat16 d_Blo[RR * 320];
__device__ unsigned d_bitmap[NN * (NN / 32)];
__device__ int      d_deg[NN];
__device__ int      d_rowptr[NN + 1];
__device__ int      d_col[2 * EE];
__device__ float    d_dinv[NN];
__device__ float    d_cat[NN * CATD];
__device__ int      d_is64;

// ================= PTX helpers (sm_80-compatible only) =================
__device__ __forceinline__ uint32_t s2u(const void* p) {
    uint32_t a;
    asm("{ .reg .u64 t; cvta.to.shared.u64 t, %1; cvt.u32.u64 %0, t; }" : "=r"(a) : "l"(p));
    return a;
}
#define LDSM4(r, addr) \
    asm volatile("ldmatrix.sync.aligned.m8n8.x4.shared.b16 {%0,%1,%2,%3}, [%4];" \
        : "=r"((r)[0]), "=r"((r)[1]), "=r"((r)[2]), "=r"((r)[3]) : "r"(addr))

#define MMA16816(d, a, b0, b1) \
    asm volatile("mma.sync.aligned.m16n8k16.row.col.f32.bf16.bf16.f32 " \
        "{%0,%1,%2,%3}, {%4,%5,%6,%7}, {%8,%9}, {%0,%1,%2,%3};" \
        : "+f"((d)[0]), "+f"((d)[1]), "+f"((d)[2]), "+f"((d)[3]) \
        : "r"((a)[0]), "r"((a)[1]), "r"((a)[2]), "r"((a)[3]), "r"(b0), "r"(b1))

#define CPA16(dst, src) \
    asm volatile("cp.async.cg.shared.global [%0], [%1], 16;" :: "r"(dst), "l"(src) : "memory")
#define CP_COMMIT asm volatile("cp.async.commit_group;" ::: "memory")
#define CP_WAIT0  asm volatile("cp.async.wait_group 0;" ::: "memory")

__device__ __forceinline__ float ftanh(float v) {
    float a = fabsf(v);
    float e = __expf(-2.0f * a);
    float r = __fdividef(1.0f - e, 1.0f + e);
    return copysignf(r, v);
}

// ---------------- dtype detection for edge_index (int32 vs int64) ----------------
__global__ void detect_kernel(const unsigned* __restrict__ w) {
    if (threadIdx.x == 0) {
        int f = 1;
        for (int i = 0; i < 64; i++) {
            if (w[2 * i + 1] != 0u) { f = 0; break; }
        }
        d_is64 = f;
    }
}

// ---------------- zero bitmap ----------------
__global__ void zero_kernel() {
    int i = blockIdx.x * blockDim.x + threadIdx.x;  // 2097152 threads
    d_bitmap[i] = 0u;
}

// ---------------- weight conversion to bf16 hi/lo ----------------
__global__ void wconv_kernel(const float* __restrict__ Win, const float* __restrict__ Wres) {
    int i = blockIdx.x * blockDim.x + threadIdx.x;
    if (i >= 256 * 320) return;
    int r = i / 320, k = i % 320;
    float v = (k < DIN) ? Win[r * DIN + k] : Wres[r * RR + (k - DIN)];
    __nv_bfloat16 h = __float2bfloat16(v);
    d_Bhi[i] = h;
    d_Blo[i] = __float2bfloat16(v - __bfloat162float(h));
}

// ---------------- build binary adjacency bitmap ----------------
__global__ void pass1_kernel(const void* __restrict__ ei) {
    int i = blockIdx.x * blockDim.x + threadIdx.x;
    if (i >= 2 * EE) return;
    int u, v;
    if (d_is64) {
        const long long* p = (const long long*)ei;
        if (i < EE) { u = (int)p[i]; v = (int)p[EE + i]; }
        else        { u = (int)p[i]; v = (int)p[i - EE]; }
    } else {
        const int* p = (const int*)ei;
        if (i < EE) { u = p[i]; v = p[EE + i]; }
        else        { u = p[i]; v = p[i - EE]; }
    }
    atomicOr(&d_bitmap[(u << 8) + (v >> 5)], 1u << (v & 31));
}

// ---------------- degree + dinv ----------------
__global__ void degdinv_kernel() {
    int gw = (blockIdx.x * blockDim.x + threadIdx.x) >> 5;
    int lane = threadIdx.x & 31;
    if (gw >= NN) return;
    const unsigned* row = d_bitmap + gw * 256;
    int c = 0;
#pragma unroll
    for (int j = 0; j < 8; j++) c += __popc(row[lane * 8 + j]);
#pragma unroll
    for (int o = 16; o; o >>= 1) c += __shfl_xor_sync(0xffffffffu, c, o);
    if (lane == 0) {
        d_deg[gw] = c;
        d_dinv[gw] = (c > 0) ? fminf(1e6f, 1.0f / sqrtf((float)c)) : 0.0f;
    }
}

// ---------------- exclusive scan -> rowptr ----------------
__global__ void scan_kernel() {
    __shared__ int s[1024];
    int tid = threadIdx.x;
    int loc[8]; int sum = 0;
#pragma unroll
    for (int j = 0; j < 8; j++) { loc[j] = d_deg[tid * 8 + j]; sum += loc[j]; }
    s[tid] = sum;
    __syncthreads();
    for (int off = 1; off < 1024; off <<= 1) {
        int t = 0;
        if (tid >= off) t = s[tid - off];
        __syncthreads();
        s[tid] += t;
        __syncthreads();
    }
    int run = (tid == 0) ? 0 : s[tid - 1];
    if (tid == 0) d_rowptr[0] = 0;
#pragma unroll
    for (int j = 0; j < 8; j++) { run += loc[j]; d_rowptr[tid * 8 + j + 1] = run; }
}

// ---------------- extract CSR cols ----------------
__global__ void extract_kernel() {
    int gw = (blockIdx.x * blockDim.x + threadIdx.x) >> 5;
    int lane = threadIdx.x & 31;
    if (gw >= NN) return;
    const unsigned* row = d_bitmap + gw * 256;
    unsigned w[8]; int cnt = 0;
#pragma unroll
    for (int j = 0; j < 8; j++) { w[j] = row[lane * 8 + j]; cnt += __popc(w[j]); }
    int off = cnt;
#pragma unroll
    for (int d = 1; d < 32; d <<= 1) {
        int t = __shfl_up_sync(0xffffffffu, off, d);
        if (lane >= d) off += t;
    }
    off -= cnt;
    int pos = d_rowptr[gw] + off;
#pragma unroll
    for (int j = 0; j < 8; j++) {
        unsigned m = w[j];
        int base = (lane * 8 + j) << 5;
        while (m) {
            int b = __ffs(m) - 1;
            d_col[pos++] = base + b;
            m &= m - 1;
        }
    }
}

// ================= persistent ESN: all 64 steps in one kernel =================
// CTA = 64 rows (independent nodes) x full 256 reservoir dims; h lives in registers;
// bf16 hi/lo of h lives in the resident smem A region (conflict-free 80B rows).
// B (weights, same every step, L2-resident) streamed via 2-stage cp.async.

__device__ __forceinline__ void copyB_chunk(int c, uint32_t dstbase, int tid) {
#pragma unroll
    for (int i = 0; i < 4; i++) {
        int G = tid * 4 + i;          // 0..1023
        int row = G >> 2, q = G & 3;  // 256 rows x 4 x 16B granules
        size_t e = (size_t)row * 320 + c * 32 + q * 8;
        uint32_t d = dstbase + row * AROW + q * 16;
        CPA16(d,          (const char*)d_Bhi + e * 2);
        CPA16(d + BTYPE,  (const char*)d_Blo + e * 2);
    }
}

__global__ void __launch_bounds__(256)
step_persist(const float* __restrict__ x)
{
    extern __shared__ __align__(128) char smem[];
    const int tid = threadIdx.x, wid = tid >> 5, lane = tid & 31;
    const int m0 = blockIdx.x * MTILE;
    const int warpM = (wid & 1) * 32;
    const int warpN = (wid >> 1) * 64;
    const uint32_t Ab = s2u(smem);
    const uint32_t Bb = Ab + AREG;

    // zero resident A region (h = 0 at t=0)
    for (int i = tid; i < AREG / 16; i += 256)
        *(uint4*)(smem + i * 16) = make_uint4(0, 0, 0, 0);

    float h[2][8][4], acc[2][8][4];
#pragma unroll
    for (int mi = 0; mi < 2; mi++)
#pragma unroll
        for (int ni = 0; ni < 8; ni++)
#pragma unroll
            for (int q = 0; q < 4; q++) { h[mi][ni][q] = 0.0f; acc[mi][ni][q] = 0.0f; }
    __syncthreads();

#pragma unroll 1
    for (int t = 0; t < TT; t++) {
        // ---- stage x chunks 0,1 (fp32 -> bf16 hi/lo) into A region ----
#pragma unroll
        for (int i = 0; i < 4; i++) {
            int g = tid * 4 + i;           // 0..1023
            int row = g >> 4, q = g & 15;  // 64 rows x 16 float4
            float4 v = *(const float4*)(x + (size_t)(m0 + row) * (TT * DIN) + t * DIN + q * 4);
            union { __nv_bfloat16 bb[4]; uint2 u; } uh, ul;
            uh.bb[0] = __float2bfloat16(v.x); uh.bb[1] = __float2bfloat16(v.y);
            uh.bb[2] = __float2bfloat16(v.z); uh.bb[3] = __float2bfloat16(v.w);
            ul.bb[0] = __float2bfloat16(v.x - __bfloat162float(uh.bb[0]));
            ul.bb[1] = __float2bfloat16(v.y - __bfloat162float(uh.bb[1]));
            ul.bb[2] = __float2bfloat16(v.z - __bfloat162float(uh.bb[2]));
            ul.bb[3] = __float2bfloat16(v.w - __bfloat162float(uh.bb[3]));
            int chunk = q >> 3, kc = (q & 7) * 4;
            uint32_t off = (uint32_t)chunk * ACH2 + row * AROW + kc * 2;
            *(uint2*)(smem + off) = uh.u;
            *(uint2*)(smem + off + ACH) = ul.u;
        }
        // prefetch B chunk 0
        copyB_chunk(0, Bb, tid);
        CP_COMMIT;

#pragma unroll 1
        for (int c = 0; c < 10; c++) {
            CP_WAIT0;
            __syncthreads();   // chunk c visible to all; prev buffer free to overwrite
            if (c < 9) { copyB_chunk(c + 1, Bb + ((c + 1) & 1) * BBUF, tid); CP_COMMIT; }

            const uint32_t Ac = Ab + (uint32_t)c * ACH2;
            const uint32_t Bc = Bb + (c & 1) * BBUF;
#pragma unroll
            for (int ks = 0; ks < 2; ks++) {
                const int kb = ks * 32;  // byte offset of the k16 slice
                uint32_t ah[2][4], al[2][4];
#pragma unroll
                for (int mi = 0; mi < 2; mi++) {
                    int row = warpM + mi * 16 + (lane & 15);
                    uint32_t ad = Ac + row * AROW + kb + (lane >> 4) * 16;
                    LDSM4(ah[mi], ad);
                    LDSM4(al[mi], ad + ACH);
                }
#pragma unroll
                for (int nb = 0; nb < 4; nb++) {
                    int row = warpN + nb * 16 + ((lane >> 4) << 3) + (lane & 7);
                    uint32_t bd = Bc + row * AROW + kb + ((lane >> 3) & 1) * 16;
                    uint32_t bh[4], bl[4];
                    LDSM4(bh, bd);
                    LDSM4(bl, bd + BTYPE);
#pragma unroll
                    for (int mi = 0; mi < 2; mi++) {
                        MMA16816(acc[mi][nb * 2],     ah[mi], bh[0], bh[1]);
                        MMA16816(acc[mi][nb * 2],     ah[mi], bl[0], bl[1]);
                        MMA16816(acc[mi][nb * 2],     al[mi], bh[0], bh[1]);
                        MMA16816(acc[mi][nb * 2 + 1], ah[mi], bh[2], bh[3]);
                        MMA16816(acc[mi][nb * 2 + 1], ah[mi], bl[2], bl[3]);
                        MMA16816(acc[mi][nb * 2 + 1], al[mi], bh[2], bh[3]);
                    }
                }
            }
        }
        __syncthreads();  // all ldmatrix reads of A region complete

        // ---- epilogue: h = 0.7h + 0.3 tanh(acc) ----
        if (t == TT - 1) {
#pragma unroll
            for (int mi = 0; mi < 2; mi++)
#pragma unroll
                for (int ni = 0; ni < 8; ni++)
#pragma unroll
                    for (int rr = 0; rr < 2; rr++) {
                        int row = m0 + warpM + mi * 16 + (lane >> 2) + rr * 8;
                        int col = warpN + ni * 8 + (lane & 3) * 2;
                        float o0 = 0.7f * h[mi][ni][rr * 2 + 0] + 0.3f * ftanh(acc[mi][ni][rr * 2 + 0]);
                        float o1 = 0.7f * h[mi][ni][rr * 2 + 1] + 0.3f * ftanh(acc[mi][ni][rr * 2 + 1]);
                        *(float2*)&d_cat[(size_t)row * CATD + col] = make_float2(o0, o1);
                    }
        } else {
#pragma unroll
            for (int mi = 0; mi < 2; mi++)
#pragma unroll
                for (int ni = 0; ni < 8; ni++)
#pragma unroll
                    for (int rr = 0; rr < 2; rr++) {
                        int rloc = warpM + mi * 16 + (lane >> 2) + rr * 8;
                        int col = warpN + ni * 8 + (lane & 3) * 2;
                        float o0 = 0.7f * h[mi][ni][rr * 2 + 0] + 0.3f * ftanh(acc[mi][ni][rr * 2 + 0]);
                        float o1 = 0.7f * h[mi][ni][rr * 2 + 1] + 0.3f * ftanh(acc[mi][ni][rr * 2 + 1]);
                        h[mi][ni][rr * 2 + 0] = o0;
                        h[mi][ni][rr * 2 + 1] = o1;
                        acc[mi][ni][rr * 2 + 0] = 0.0f;
                        acc[mi][ni][rr * 2 + 1] = 0.0f;
                        union { __nv_bfloat16 bb[2]; uint32_t u; } uh, ul;
                        uh.bb[0] = __float2bfloat16(o0);
                        uh.bb[1] = __float2bfloat16(o1);
                        ul.bb[0] = __float2bfloat16(o0 - __bfloat162float(uh.bb[0]));
                        ul.bb[1] = __float2bfloat16(o1 - __bfloat162float(uh.bb[1]));
                        // h occupies K range [64,320) => chunk 2 + col/32
                        uint32_t off = (uint32_t)(2 + (col >> 5)) * ACH2 + rloc * AROW + (col & 31) * 2;
                        *(uint32_t*)(smem + off) = uh.u;
                        *(uint32_t*)(smem + off + ACH) = ul.u;
                    }
        }
        // next iteration's in-loop __syncthreads (at c=0..2) publishes these writes
        // before any ldmatrix consumes them
    }
}

// ---------------- SpMM hop ----------------
__global__ __launch_bounds__(256) void spmm_kernel(int hop) {
    int u = blockIdx.x;
    int r = threadIdx.x;
    int s = d_rowptr[u], e = d_rowptr[u + 1];
    const float* src = d_cat + (hop - 1) * RR + r;
    float acc = 0.0f;
    int i = s;
    for (; i + 4 <= e; i += 4) {
        int v0 = d_col[i], v1 = d_col[i + 1], v2 = d_col[i + 2], v3 = d_col[i + 3];
        float x0 = src[(size_t)v0 * CATD];
        float x1 = src[(size_t)v1 * CATD];
        float x2 = src[(size_t)v2 * CATD];
        float x3 = src[(size_t)v3 * CATD];
        acc += d_dinv[v0] * x0 + d_dinv[v1] * x1 + d_dinv[v2] * x2 + d_dinv[v3] * x3;
    }
    for (; i < e; i++) {
        int v = d_col[i];
        acc += d_dinv[v] * src[(size_t)v * CATD];
    }
    d_cat[u * CATD + hop * RR + r] = d_dinv[u] * acc;
}

// ---------------- readout (fp32 SIMT) ----------------
__global__ __launch_bounds__(256) void readout_kernel(
    const float* __restrict__ W1, const float* __restrict__ b1,
    const float* __restrict__ W2, const float* __restrict__ b2,
    const float* __restrict__ gamma, const float* __restrict__ beta,
    float* __restrict__ out)
{
    __shared__ float As1[16][64 + 4];
    __shared__ float Bs1[16][128 + 4];
    __shared__ float z1t[128][64 + 4];

    int tid = threadIdx.x;
    int n0 = blockIdx.x * 64;

    int rg = tid >> 5;
    int cg = tid & 31;
    float acc[8][4];
#pragma unroll
    for (int i = 0; i < 8; i++)
#pragma unroll
        for (int j = 0; j < 4; j++) acc[i][j] = 0.0f;

    int lm = tid >> 2;
    int lka = (tid & 3) * 4;
    int lj = tid >> 1;
    int lkb = (tid & 1) * 8;
    const float* arow = d_cat + (n0 + lm) * CATD;
    const float* brow = W1 + lj * CATD;

#pragma unroll 1
    for (int kt = 0; kt < 64; kt++) {
        int k0 = kt * 16;
        float4 va = *(const float4*)(arow + k0 + lka);
        As1[lka + 0][lm] = va.x; As1[lka + 1][lm] = va.y;
        As1[lka + 2][lm] = va.z; As1[lka + 3][lm] = va.w;
        float4 vb0 = *(const float4*)(brow + k0 + lkb);
        float4 vb1 = *(const float4*)(brow + k0 + lkb + 4);
        Bs1[lkb + 0][lj] = vb0.x; Bs1[lkb + 1][lj] = vb0.y;
        Bs1[lkb + 2][lj] = vb0.z; Bs1[lkb + 3][lj] = vb0.w;
        Bs1[lkb + 4][lj] = vb1.x; Bs1[lkb + 5][lj] = vb1.y;
        Bs1[lkb + 6][lj] = vb1.z; Bs1[lkb + 7][lj] = vb1.w;
        __syncthreads();
#pragma unroll
        for (int kk = 0; kk < 16; kk++) {
            float4 a0 = *(const float4*)&As1[kk][rg * 8];
            float4 a1 = *(const float4*)&As1[kk][rg * 8 + 4];
            float4 b4 = *(const float4*)&Bs1[kk][cg * 4];
            float av[8] = {a0.x, a0.y, a0.z, a0.w, a1.x, a1.y, a1.z, a1.w};
            float bv[4] = {b4.x, b4.y, b4.z, b4.w};
#pragma unroll
            for (int i = 0; i < 8; i++)
#pragma unroll
                for (int j = 0; j < 4; j++) acc[i][j] += av[i] * bv[j];
        }
        __syncthreads();
    }

#pragma unroll
    for (int i = 0; i < 8; i++) {
#pragma unroll
        for (int j = 0; j < 4; j++) {
            int col = cg * 4 + j;
            int row = rg * 8 + i;
            float v = acc[i][j] + b1[col];
            float g = 0.5f * v * (1.0f + erff(v * 0.70710678118654752f));
            z1t[col][row] = g;
        }
    }
    __syncthreads();

    int rg2 = tid >> 4;
    int cg2 = tid & 15;
    float acc2[4][4];
#pragma unroll
    for (int i = 0; i < 4; i++)
#pragma unroll
        for (int j = 0; j < 4; j++) acc2[i][j] = 0.0f;

#pragma unroll 4
    for (int k = 0; k < 128; k++) {
        float4 a = *(const float4*)&z1t[k][rg2 * 4];
        float av[4] = {a.x, a.y, a.z, a.w};
#pragma unroll
        for (int j = 0; j < 4; j++) {
            float b = __ldg(&W2[(cg2 * 4 + j) * 128 + k]);
#pragma unroll
            for (int i = 0; i < 4; i++) acc2[i][j] += av[i] * b;
        }
    }

    float vals[4][4];
#pragma unroll
    for (int i = 0; i < 4; i++)
#pragma unroll
        for (int j = 0; j < 4; j++) vals[i][j] = acc2[i][j] + b2[cg2 * 4 + j];

    float mean[4], var[4];
#pragma unroll
    for (int i = 0; i < 4; i++) {
        float s = vals[i][0] + vals[i][1] + vals[i][2] + vals[i][3];
#pragma unroll
        for (int o = 8; o; o >>= 1) s += __shfl_xor_sync(0xffffffffu, s, o);
        mean[i] = s * (1.0f / 64.0f);
    }
#pragma unroll
    for (int i = 0; i < 4; i++) {
        float s = 0.0f;
#pragma unroll
        for (int j = 0; j < 4; j++) {
            float d = vals[i][j] - mean[i];
            s += d * d;
        }
#pragma unroll
        for (int o = 8; o; o >>= 1) s += __shfl_xor_sync(0xffffffffu, s, o);
        var[i] = s * (1.0f / 64.0f);
    }

#pragma unroll
    for (int i = 0; i < 4; i++) {
        int node = n0 + rg2 * 4 + i;
        float inv = 1.0f / sqrtf(var[i] + 1e-5f);
        float4 o;
        float g0 = gamma[cg2 * 4 + 0], g1 = gamma[cg2 * 4 + 1];
        float g2 = gamma[cg2 * 4 + 2], g3 = gamma[cg2 * 4 + 3];
        float be0 = beta[cg2 * 4 + 0], be1 = beta[cg2 * 4 + 1];
        float be2 = beta[cg2 * 4 + 2], be3 = beta[cg2 * 4 + 3];
        o.x = (vals[i][0] - mean[i]) * inv * g0 + be0;
        o.y = (vals[i][1] - mean[i]) * inv * g1 + be1;
        o.z = (vals[i][2] - mean[i]) * inv * g2 + be2;
        o.w = (vals[i][3] - mean[i]) * inv * g3 + be3;
        *(float4*)&out[node * DOUT + cg2 * 4] = o;
    }
}

// ---------------- launch ----------------
extern "C" void kernel_launch(void* const* d_in, const int* in_sizes, int n_in,
                              void* d_out, int out_size) {
    const float* x     = (const float*)d_in[0];
    const void*  ei    = d_in[1];
    const float* Win   = (const float*)d_in[2];
    const float* Wres  = (const float*)d_in[3];
    const float* W1    = (const float*)d_in[4];
    const float* b1    = (const float*)d_in[5];
    const float* W2    = (const float*)d_in[6];
    const float* b2    = (const float*)d_in[7];
    const float* gamma = (const float*)d_in[8];
    const float* beta  = (const float*)d_in[9];
    float* out = (float*)d_out;

    (void)cudaFuncSetAttribute(step_persist, cudaFuncAttributeMaxDynamicSharedMemorySize, STEP_SMEM);

    detect_kernel<<<1, 32>>>((const unsigned*)ei);
    zero_kernel<<<4096, 512>>>();
    wconv_kernel<<<320, 256>>>(Win, Wres);
    pass1_kernel<<<1024, 256>>>(ei);
    degdinv_kernel<<<1024, 256>>>();
    scan_kernel<<<1, 1024>>>();
    extract_kernel<<<1024, 256>>>();

    step_persist<<<128, 256, STEP_SMEM>>>(x);

    for (int hop = 1; hop <= 3; hop++)
        spmm_kernel<<<NN, 256>>>(hop);

    readout_kernel<<<128, 256>>>(W1, b1, W2, b2, gamma, beta, out);
}